// round 1
// baseline (speedup 1.0000x reference)
#include <cuda_runtime.h>
#include <cstdint>

// Problem constants
#define B_  16
#define L_  1024
#define U_  512
#define M_  (B_*L_)      // 16384 rows

// ---------------------------------------------------------------------------
// Scratch (device globals; no allocation allowed)
// ---------------------------------------------------------------------------
__device__ float g_x0[M_*U_];          // 32 MB
__device__ float g_x1[M_*U_];          // 32 MB
__device__ float g_t [M_*U_];          // 32 MB (t / z)
__device__ float g_c [M_*U_];          // 32 MB (c / r)
__device__ float g_A [(size_t)B_*L_*L_]; // 64 MB scores
__device__ float g_s1[M_];
__device__ float g_s2[M_];
__device__ float g_cat[(size_t)M_*2*U_]; // 64 MB concat

// ---------------------------------------------------------------------------
// Generic NN SGEMM: C = act(A[M,K] @ B[K,N] + bias), optional batch strides.
// BM=BN=128, BK=8, 256 threads, 8x8 microtile, interleaved columns (tx+16j).
// All dims here are multiples of the tile sizes (hardcoded problem shapes).
// ---------------------------------------------------------------------------
#define BM 128
#define BN 128
#define BK 8

__global__ __launch_bounds__(256) void gemm_nn(
    const float* __restrict__ Ag, const float* __restrict__ Bg,
    const float* __restrict__ bias, float* __restrict__ Cg,
    int Mi, int Ni, int Ki,
    long sA, long sB, long sC, int act)
{
    __shared__ float As[BK][BM];
    __shared__ float Bs[BK][BN];

    const float* A = Ag + (long)blockIdx.z * sA;
    const float* Bm = Bg + (long)blockIdx.z * sB;
    float*       C = Cg + (long)blockIdx.z * sC;

    const int bm = blockIdx.y * BM;
    const int bn = blockIdx.x * BN;
    const int tid = threadIdx.x;

    const int arow = tid >> 1;           // 0..127
    const int acol = (tid & 1) * 4;      // 0 or 4
    const int brow = tid >> 5;           // 0..7
    const int bcol = (tid & 31) * 4;     // 0..124
    const int ty = tid >> 4;             // 0..15
    const int tx = tid & 15;             // 0..15

    float acc[8][8];
    #pragma unroll
    for (int i = 0; i < 8; i++)
        #pragma unroll
        for (int j = 0; j < 8; j++) acc[i][j] = 0.f;

    for (int k0 = 0; k0 < Ki; k0 += BK) {
        float4 av = *(const float4*)(A + (long)(bm + arow) * Ki + k0 + acol);
        As[acol + 0][arow] = av.x;
        As[acol + 1][arow] = av.y;
        As[acol + 2][arow] = av.z;
        As[acol + 3][arow] = av.w;

        float4 bv = *(const float4*)(Bm + (long)(k0 + brow) * Ni + bn + bcol);
        *(float4*)&Bs[brow][bcol] = bv;
        __syncthreads();

        #pragma unroll
        for (int k = 0; k < BK; k++) {
            float a[8], b[8];
            #pragma unroll
            for (int i = 0; i < 8; i++) a[i] = As[k][ty * 8 + i];
            #pragma unroll
            for (int j = 0; j < 8; j++) b[j] = Bs[k][tx + 16 * j];
            #pragma unroll
            for (int i = 0; i < 8; i++)
                #pragma unroll
                for (int j = 0; j < 8; j++) acc[i][j] += a[i] * b[j];
        }
        __syncthreads();
    }

    #pragma unroll
    for (int i = 0; i < 8; i++) {
        const int row = bm + ty * 8 + i;
        #pragma unroll
        for (int j = 0; j < 8; j++) {
            const int col = bn + tx + 16 * j;
            float v = acc[i][j] + (bias ? bias[col] : 0.f);
            if (act == 1)      v = fmaxf(v, 0.f);
            else if (act == 2) v = 1.f / (1.f + __expf(-v));
            C[(long)row * Ni + col] = v;
        }
    }
}

// ---------------------------------------------------------------------------
// Scores NT-GEMM (batched over blockIdx.z):
//   A[b,i,j] = relu( sum_d x[b,i,d]*w3[d]*x[b,j,d] + s1[b,i] + s2[b,j] + ab0 )
// w3 scaling folded into the A-tile smem load.
// ---------------------------------------------------------------------------
__global__ __launch_bounds__(256) void scores_nt(
    const float* __restrict__ xg, const float* __restrict__ w3,
    const float* __restrict__ s1g, const float* __restrict__ s2g,
    const float* __restrict__ ab, float* __restrict__ Ag)
{
    __shared__ float As[BK][BM];
    __shared__ float Bs[BK][BN];

    const int bz = blockIdx.z;
    const float* x  = xg  + (long)bz * L_ * U_;
    const float* s1 = s1g + bz * L_;
    const float* s2 = s2g + bz * L_;
    float*       C  = Ag  + (long)bz * L_ * L_;

    const int bm = blockIdx.y * BM;
    const int bn = blockIdx.x * BN;
    const int tid = threadIdx.x;
    const int arow = tid >> 1;
    const int acol = (tid & 1) * 4;
    const int ty = tid >> 4;
    const int tx = tid & 15;
    const float ab0 = ab[0];

    float acc[8][8];
    #pragma unroll
    for (int i = 0; i < 8; i++)
        #pragma unroll
        for (int j = 0; j < 8; j++) acc[i][j] = 0.f;

    for (int k0 = 0; k0 < U_; k0 += BK) {
        float4 av = *(const float4*)(x + (long)(bm + arow) * U_ + k0 + acol);
        float4 wv = *(const float4*)(w3 + k0 + acol);
        As[acol + 0][arow] = av.x * wv.x;
        As[acol + 1][arow] = av.y * wv.y;
        As[acol + 2][arow] = av.z * wv.z;
        As[acol + 3][arow] = av.w * wv.w;

        float4 bv = *(const float4*)(x + (long)(bn + arow) * U_ + k0 + acol);
        Bs[acol + 0][arow] = bv.x;
        Bs[acol + 1][arow] = bv.y;
        Bs[acol + 2][arow] = bv.z;
        Bs[acol + 3][arow] = bv.w;
        __syncthreads();

        #pragma unroll
        for (int k = 0; k < BK; k++) {
            float a[8], b[8];
            #pragma unroll
            for (int i = 0; i < 8; i++) a[i] = As[k][ty * 8 + i];
            #pragma unroll
            for (int j = 0; j < 8; j++) b[j] = Bs[k][tx + 16 * j];
            #pragma unroll
            for (int i = 0; i < 8; i++)
                #pragma unroll
                for (int j = 0; j < 8; j++) acc[i][j] += a[i] * b[j];
        }
        __syncthreads();
    }

    #pragma unroll
    for (int i = 0; i < 8; i++) {
        const int row = bm + ty * 8 + i;
        const float s1v = s1[row];
        #pragma unroll
        for (int j = 0; j < 8; j++) {
            const int col = bn + tx + 16 * j;
            float v = acc[i][j] + s1v + s2[col] + ab0;
            v = fmaxf(v, 0.f);
            C[(long)row * L_ + col] = v;
        }
    }
}

// ---------------------------------------------------------------------------
// s1[b,i] = x[b,i,:]·w1 ; s2[b,i] = x[b,i,:]·w2   (one warp per row)
// ---------------------------------------------------------------------------
__global__ __launch_bounds__(256) void s1s2_kernel(
    const float* __restrict__ x, const float* __restrict__ aW,
    float* __restrict__ s1, float* __restrict__ s2)
{
    const int row  = blockIdx.x * 8 + (threadIdx.x >> 5);
    const int lane = threadIdx.x & 31;
    const float* xr = x + (long)row * U_;
    float a = 0.f, b = 0.f;
    for (int d = lane; d < U_; d += 32) {
        const float xv = xr[d];
        a += xv * aW[d];
        b += xv * aW[U_ + d];
    }
    #pragma unroll
    for (int o = 16; o > 0; o >>= 1) {
        a += __shfl_xor_sync(0xffffffffu, a, o);
        b += __shfl_xor_sync(0xffffffffu, b, o);
    }
    if (lane == 0) { s1[row] = a; s2[row] = b; }
}

// ---------------------------------------------------------------------------
// In-place row softmax over length L_ (one block per row)
// ---------------------------------------------------------------------------
__global__ __launch_bounds__(256) void softmax_kernel(float* __restrict__ A)
{
    float* row = A + (long)blockIdx.x * L_;
    const int tid = threadIdx.x;
    __shared__ float red[256];

    float m = -1e30f;
    for (int i = tid; i < L_; i += 256) m = fmaxf(m, row[i]);
    red[tid] = m; __syncthreads();
    for (int s = 128; s > 0; s >>= 1) {
        if (tid < s) red[tid] = fmaxf(red[tid], red[tid + s]);
        __syncthreads();
    }
    m = red[0]; __syncthreads();

    float sum = 0.f;
    for (int i = tid; i < L_; i += 256) {
        const float e = __expf(row[i] - m);
        row[i] = e;
        sum += e;
    }
    red[tid] = sum; __syncthreads();
    for (int s = 128; s > 0; s >>= 1) {
        if (tid < s) red[tid] += red[tid + s];
        __syncthreads();
    }
    const float inv = 1.f / red[0];
    for (int i = tid; i < L_; i += 256) row[i] *= inv;
}

// ---------------------------------------------------------------------------
// Elementwise glue
// ---------------------------------------------------------------------------
__global__ __launch_bounds__(256) void highway_combine(
    const float* __restrict__ t, const float* __restrict__ c,
    const float* __restrict__ xin, float* __restrict__ xout, int n4)
{
    const int i = blockIdx.x * blockDim.x + threadIdx.x;
    if (i >= n4) return;
    const float4 tv = ((const float4*)t)[i];
    const float4 cv = ((const float4*)c)[i];
    const float4 xv = ((const float4*)xin)[i];
    float4 o;
    o.x = tv.x * cv.x + xv.x * (1.f - cv.x);
    o.y = tv.y * cv.y + xv.y * (1.f - cv.y);
    o.z = tv.z * cv.z + xv.z * (1.f - cv.z);
    o.w = tv.w * cv.w + xv.w * (1.f - cv.w);
    ((float4*)xout)[i] = o;
}

__global__ __launch_bounds__(256) void concat_kernel(
    const float* __restrict__ a, const float* __restrict__ b,
    float* __restrict__ cat)
{
    const int gid = blockIdx.x * blockDim.x + threadIdx.x; // over M_*2U/4
    const int c4 = gid & 255;       // 0..255 float4-cols of the 1024-wide row
    const int m  = gid >> 8;
    float4 v;
    if (c4 < 128) v = *(const float4*)(a + (long)m * U_   + c4 * 4);
    else          v = *(const float4*)(b + (long)m * U_   + (c4 - 128) * 4);
    *(float4*)(cat + (long)m * (2 * U_) + c4 * 4) = v;
}

__global__ __launch_bounds__(256) void final_kernel(
    const float* __restrict__ r, const float* __restrict__ z,
    const float* __restrict__ inp, float* __restrict__ out, int n4)
{
    const int i = blockIdx.x * blockDim.x + threadIdx.x;
    if (i >= n4) return;
    const float4 rv = ((const float4*)r)[i];
    const float4 zv = ((const float4*)z)[i];
    const float4 iv = ((const float4*)inp)[i];
    float4 o;
    o.x = rv.x * iv.x + zv.x * zv.x;
    o.y = rv.y * iv.y + zv.y * zv.y;
    o.z = rv.z * iv.z + zv.z * zv.z;
    o.w = rv.w * iv.w + zv.w * zv.w;
    ((float4*)out)[i] = o;
}

// ---------------------------------------------------------------------------
// Launch
// ---------------------------------------------------------------------------
extern "C" void kernel_launch(void* const* d_in, const int* in_sizes, int n_in,
                              void* d_out, int out_size)
{
    (void)in_sizes; (void)n_in; (void)out_size;
    const float* inputs = (const float*)d_in[0];
    const float* tW     = (const float*)d_in[1];
    const float* tb     = (const float*)d_in[2];
    const float* cW     = (const float*)d_in[3];
    const float* cb     = (const float*)d_in[4];
    const float* aW     = (const float*)d_in[5];
    const float* ab     = (const float*)d_in[6];
    const float* frW    = (const float*)d_in[7];
    const float* frb    = (const float*)d_in[8];
    const float* ffW    = (const float*)d_in[9];
    const float* ffb    = (const float*)d_in[10];
    float* out = (float*)d_out;

    float *x0, *x1, *t, *c, *Amat, *s1, *s2, *cat;
    cudaGetSymbolAddress((void**)&x0,  g_x0);
    cudaGetSymbolAddress((void**)&x1,  g_x1);
    cudaGetSymbolAddress((void**)&t,   g_t);
    cudaGetSymbolAddress((void**)&c,   g_c);
    cudaGetSymbolAddress((void**)&Amat,g_A);
    cudaGetSymbolAddress((void**)&s1,  g_s1);
    cudaGetSymbolAddress((void**)&s2,  g_s2);
    cudaGetSymbolAddress((void**)&cat, g_cat);

    const int n4   = M_ * U_ / 4;          // 2M float4s
    const int ewg  = (n4 + 255) / 256;

    dim3 gHW(U_ / BN, M_ / BM, 1);         // (4,128)
    // Highway layer 0: inputs -> x0
    gemm_nn<<<gHW, 256>>>(inputs, tW,            tb,       t, M_, U_, U_, 0, 0, 0, 1);
    gemm_nn<<<gHW, 256>>>(inputs, cW,            cb,       c, M_, U_, U_, 0, 0, 0, 2);
    highway_combine<<<ewg, 256>>>(t, c, inputs, x0, n4);
    // Highway layer 1: x0 -> x1
    gemm_nn<<<gHW, 256>>>(x0, tW + U_ * U_,      tb + U_,  t, M_, U_, U_, 0, 0, 0, 1);
    gemm_nn<<<gHW, 256>>>(x0, cW + U_ * U_,      cb + U_,  c, M_, U_, U_, 0, 0, 0, 2);
    highway_combine<<<ewg, 256>>>(t, c, x0, x1, n4);

    // s1, s2
    s1s2_kernel<<<M_ / 8, 256>>>(x1, aW, s1, s2);

    // scores: A[b] = relu((x1*w3) @ x1^T + s1 + s2 + ab)
    dim3 gS(L_ / BN, L_ / BM, B_);         // (8,8,16)
    scores_nt<<<gS, 256>>>(x1, aW + 2 * U_, s1, s2, ab, Amat);

    // softmax rows
    softmax_kernel<<<M_, 256>>>(Amat);

    // att = P @ x1  -> x0
    dim3 gAtt(U_ / BN, L_ / BM, B_);       // (4,8,16)
    gemm_nn<<<gAtt, 256>>>(Amat, x1, nullptr, x0, L_, U_, L_,
                           (long)L_ * L_, (long)L_ * U_, (long)L_ * U_, 0);

    // concat [inputs, att]
    const int cg = (M_ * 2 * U_ / 4 + 255) / 256;
    concat_kernel<<<cg, 256>>>(inputs, x0, cat);

    // z (into t) and r (into c)
    gemm_nn<<<gHW, 256>>>(cat, ffW, ffb, t, M_, U_, 2 * U_, 0, 0, 0, 2);
    gemm_nn<<<gHW, 256>>>(cat, frW, frb, c, M_, U_, 2 * U_, 0, 0, 0, 2);

    // out = r*inputs + z*z
    final_kernel<<<ewg, 256>>>(c, t, inputs, out, n4);
}

// round 3
// speedup vs baseline: 2.5862x; 2.5862x over previous
#include <cuda_runtime.h>
#include <cstdint>

#define B_  16
#define L_  1024
#define U_  512
#define M_  (B_*L_)      // 16384

// ---------------------------------------------------------------------------
// Scratch (device globals; no allocation allowed)
// ---------------------------------------------------------------------------
__device__ float g_x0[M_*U_];
__device__ float g_x1[M_*U_];
__device__ float g_t [M_*U_];
__device__ float g_c [M_*U_];
__device__ float g_A [(size_t)B_*L_*L_];
__device__ float g_s1[M_];
__device__ float g_s2[M_];
__device__ float g_cat[(size_t)M_*2*U_];
__device__ float g_tWt[2*U_*U_];
__device__ float g_cWt[2*U_*U_];
__device__ float g_ffWt[2*U_*U_];   // [512][1024]
__device__ float g_frWt[2*U_*U_];   // [512][1024]
__device__ float g_x1t[M_*U_];      // per-batch [512][1024]

// ---------------------------------------------------------------------------
// PTX helpers (all baseline sm_80-era: compile at compute_103)
// ---------------------------------------------------------------------------
__device__ __forceinline__ uint32_t smem_u32(const void* p) {
    uint32_t a;
    asm("{ .reg .u64 t; cvta.to.shared.u64 t, %1; cvt.u32.u64 %0, t; }"
        : "=r"(a) : "l"(p));
    return a;
}
__device__ __forceinline__ void cpasync16(uint32_t dst, const void* src) {
    asm volatile("cp.async.cg.shared.global [%0], [%1], 16;"
                 :: "r"(dst), "l"(src));
}
#define CP_COMMIT() asm volatile("cp.async.commit_group;" ::: "memory")
#define CP_WAIT(n)  asm volatile("cp.async.wait_group %0;" :: "n"(n) : "memory")

__device__ __forceinline__ void mma_tf32(float* c, const uint32_t* a,
                                         uint32_t b0, uint32_t b1) {
    asm volatile(
        "mma.sync.aligned.m16n8k8.row.col.f32.tf32.tf32.f32 "
        "{%0,%1,%2,%3}, {%4,%5,%6,%7}, {%8,%9}, {%0,%1,%2,%3};"
        : "+f"(c[0]), "+f"(c[1]), "+f"(c[2]), "+f"(c[3])
        : "r"(a[0]), "r"(a[1]), "r"(a[2]), "r"(a[3]), "r"(b0), "r"(b1));
}

// tf32 round-to-nearest on load
__device__ __forceinline__ uint32_t R32(float x) {
    return __float_as_uint(x) + 0x1000u;
}

// ---------------------------------------------------------------------------
// Tensor-core tf32 GEMM:
//   C[M,N] = act( sum_k A[m,k]*Bt[n,k] + rowbias[m] + colbias[n] + addc )
// A row-major [*, lda]; Bt row-major [N, K] (both K contiguous).
// Grid (N/128, M/128, batch), 256 threads, warp tile 64x32 (m16n8k8 x 4x4).
// Double-buffered cp.async pipeline, KC=32.
// ---------------------------------------------------------------------------
#define KC 32
#define LR 36          // padded smem row (floats)
#define STAGE_F (128*LR)

__global__ __launch_bounds__(256) void gemm_mma(
    const float* __restrict__ A,  long lda, long sA,
    const float* __restrict__ Bt, long ldb, long sB,
    float* __restrict__ C, long ldc, long sC,
    int K,
    const float* __restrict__ rowbias, long srb,
    const float* __restrict__ colbias, long scb,
    const float* __restrict__ addc,
    int act)
{
    extern __shared__ float sm[];
    float* AsBase = sm;                    // 2 stages x 128 x LR
    float* BsBase = sm + 2 * STAGE_F;      // 2 stages x 128 x LR
    const uint32_t as_u32 = smem_u32(AsBase);
    const uint32_t bs_u32 = smem_u32(BsBase);

    const int tid  = threadIdx.x;
    const int wid  = tid >> 5;
    const int lane = tid & 31;
    const int grp  = lane >> 2;      // 0..7
    const int tig  = lane & 3;       // 0..3
    const int m0   = (wid >> 2) * 64;   // warp row offset in tile
    const int n0   = (wid & 3)  * 32;   // warp col offset in tile

    const int bz = blockIdx.z;
    const int bm = blockIdx.y * 128;
    const int bn = blockIdx.x * 128;

    const float* Ab = A  + (long)bz * sA;
    const float* Bb = Bt + (long)bz * sB;

    // per-thread load slots: 4 float4 per matrix per chunk
    const int lrow = tid >> 1;               // 0..127  (two threads per row)
    const int lc0  = (tid & 1) * 4;          // float4 index 0 or 4 (of 8)

    const int nch = K / KC;

    float acc[4][4][4];
    #pragma unroll
    for (int i = 0; i < 4; i++)
        #pragma unroll
        for (int j = 0; j < 4; j++)
            #pragma unroll
            for (int k = 0; k < 4; k++) acc[i][j][k] = 0.f;

    // ---- load one chunk into stage st ----
    auto load_chunk = [&](int c, int st) {
        const long gk = (long)c * KC;
        const float* ap = Ab + (long)(bm + lrow) * lda + gk + lc0 * 4;
        const float* bp = Bb + (long)(bn + lrow) * ldb + gk + lc0 * 4;
        uint32_t ad = as_u32 + (st * STAGE_F + lrow * LR + lc0 * 4) * 4;
        uint32_t bd = bs_u32 + (st * STAGE_F + lrow * LR + lc0 * 4) * 4;
        #pragma unroll
        for (int j = 0; j < 4; j++) {
            cpasync16(ad + j * 16, ap + j * 4);
            cpasync16(bd + j * 16, bp + j * 4);
        }
    };

    load_chunk(0, 0);
    CP_COMMIT();

    for (int c = 0; c < nch; c++) {
        const int st = c & 1;
        if (c + 1 < nch) { load_chunk(c + 1, st ^ 1); CP_COMMIT(); CP_WAIT(1); }
        else             { CP_WAIT(0); }
        __syncthreads();

        const float* As = AsBase + st * STAGE_F;
        const float* Bs = BsBase + st * STAGE_F;

        #pragma unroll
        for (int ks = 0; ks < 4; ks++) {
            const int k0 = ks * 8;
            uint32_t a[4][4];
            #pragma unroll
            for (int mt = 0; mt < 4; mt++) {
                const int r = m0 + mt * 16 + grp;
                a[mt][0] = R32(As[r * LR + k0 + tig]);
                a[mt][1] = R32(As[(r + 8) * LR + k0 + tig]);
                a[mt][2] = R32(As[r * LR + k0 + tig + 4]);
                a[mt][3] = R32(As[(r + 8) * LR + k0 + tig + 4]);
            }
            #pragma unroll
            for (int nt = 0; nt < 4; nt++) {
                const int nr = n0 + nt * 8 + grp;
                const uint32_t b0 = R32(Bs[nr * LR + k0 + tig]);
                const uint32_t b1 = R32(Bs[nr * LR + k0 + tig + 4]);
                #pragma unroll
                for (int mt = 0; mt < 4; mt++)
                    mma_tf32(acc[mt][nt], a[mt], b0, b1);
            }
        }
        __syncthreads();
    }

    // ---- epilogue ----
    float* Cb = C + (long)bz * sC;
    const float a0 = addc ? addc[0] : 0.f;

    #pragma unroll
    for (int mt = 0; mt < 4; mt++) {
        const int row = bm + m0 + mt * 16 + grp;
        float rb0 = a0, rb8 = a0;
        if (rowbias) {
            rb0 += rowbias[(long)bz * srb + row];
            rb8 += rowbias[(long)bz * srb + row + 8];
        }
        #pragma unroll
        for (int nt = 0; nt < 4; nt++) {
            const int col = bn + n0 + nt * 8 + tig * 2;
            float cb0 = 0.f, cb1 = 0.f;
            if (colbias) {
                cb0 = colbias[(long)bz * scb + col];
                cb1 = colbias[(long)bz * scb + col + 1];
            }
            float v0 = acc[mt][nt][0] + rb0 + cb0;
            float v1 = acc[mt][nt][1] + rb0 + cb1;
            float v2 = acc[mt][nt][2] + rb8 + cb0;
            float v3 = acc[mt][nt][3] + rb8 + cb1;
            if (act == 1) {
                v0 = fmaxf(v0, 0.f); v1 = fmaxf(v1, 0.f);
                v2 = fmaxf(v2, 0.f); v3 = fmaxf(v3, 0.f);
            } else if (act == 2) {
                v0 = 1.f / (1.f + __expf(-v0)); v1 = 1.f / (1.f + __expf(-v1));
                v2 = 1.f / (1.f + __expf(-v2)); v3 = 1.f / (1.f + __expf(-v3));
            }
            *(float2*)(Cb + (long)row * ldc + col)       = make_float2(v0, v1);
            *(float2*)(Cb + (long)(row + 8) * ldc + col) = make_float2(v2, v3);
        }
    }
}

// ---------------------------------------------------------------------------
// Batched transpose: dst[c][r] = src[r][c]; grid (C/32, R/32, batch)
// ---------------------------------------------------------------------------
__global__ __launch_bounds__(256) void transpose_k(
    const float* __restrict__ src, float* __restrict__ dst,
    int R, int Cc, long ssrc, long sdst)
{
    __shared__ float tile[32][33];
    src += (long)blockIdx.z * ssrc;
    dst += (long)blockIdx.z * sdst;
    const int r0 = blockIdx.y * 32, c0 = blockIdx.x * 32;
    const int tx = threadIdx.x & 31, ty = threadIdx.x >> 5;
    #pragma unroll
    for (int i = 0; i < 32; i += 8)
        tile[ty + i][tx] = src[(long)(r0 + ty + i) * Cc + c0 + tx];
    __syncthreads();
    #pragma unroll
    for (int i = 0; i < 32; i += 8)
        dst[(long)(c0 + ty + i) * R + r0 + tx] = tile[tx][ty + i];
}

// ---------------------------------------------------------------------------
// Small kernels
// ---------------------------------------------------------------------------
__global__ __launch_bounds__(256) void s1s2_kernel(
    const float* __restrict__ x, const float* __restrict__ aW,
    float* __restrict__ s1, float* __restrict__ s2)
{
    const int row  = blockIdx.x * 8 + (threadIdx.x >> 5);
    const int lane = threadIdx.x & 31;
    const float* xr = x + (long)row * U_;
    float a = 0.f, b = 0.f;
    for (int d = lane; d < U_; d += 32) {
        const float xv = xr[d];
        a += xv * aW[d];
        b += xv * aW[U_ + d];
    }
    #pragma unroll
    for (int o = 16; o > 0; o >>= 1) {
        a += __shfl_xor_sync(0xffffffffu, a, o);
        b += __shfl_xor_sync(0xffffffffu, b, o);
    }
    if (lane == 0) { s1[row] = a; s2[row] = b; }
}

__global__ __launch_bounds__(256) void softmax_kernel(float* __restrict__ A)
{
    float* row = A + (long)blockIdx.x * L_;
    const int tid = threadIdx.x;
    __shared__ float red[256];

    float m = -1e30f;
    for (int i = tid; i < L_; i += 256) m = fmaxf(m, row[i]);
    red[tid] = m; __syncthreads();
    for (int s = 128; s > 0; s >>= 1) {
        if (tid < s) red[tid] = fmaxf(red[tid], red[tid + s]);
        __syncthreads();
    }
    m = red[0]; __syncthreads();

    float sum = 0.f;
    for (int i = tid; i < L_; i += 256) {
        const float e = __expf(row[i] - m);
        row[i] = e;
        sum += e;
    }
    red[tid] = sum; __syncthreads();
    for (int s = 128; s > 0; s >>= 1) {
        if (tid < s) red[tid] += red[tid + s];
        __syncthreads();
    }
    const float inv = 1.f / red[0];
    for (int i = tid; i < L_; i += 256) row[i] *= inv;
}

__global__ __launch_bounds__(256) void highway_combine(
    const float* __restrict__ t, const float* __restrict__ c,
    const float* __restrict__ xin, float* __restrict__ xout, int n4)
{
    const int i = blockIdx.x * blockDim.x + threadIdx.x;
    if (i >= n4) return;
    const float4 tv = ((const float4*)t)[i];
    const float4 cv = ((const float4*)c)[i];
    const float4 xv = ((const float4*)xin)[i];
    float4 o;
    o.x = tv.x * cv.x + xv.x * (1.f - cv.x);
    o.y = tv.y * cv.y + xv.y * (1.f - cv.y);
    o.z = tv.z * cv.z + xv.z * (1.f - cv.z);
    o.w = tv.w * cv.w + xv.w * (1.f - cv.w);
    ((float4*)xout)[i] = o;
}

// xw3[m][d] = x[m][d] * w3[d]
__global__ __launch_bounds__(256) void mulw3_kernel(
    const float* __restrict__ x, const float* __restrict__ w3,
    float* __restrict__ y, int n4)
{
    const int i = blockIdx.x * blockDim.x + threadIdx.x;
    if (i >= n4) return;
    const int d4 = i & (U_ / 4 - 1);
    float4 v = ((const float4*)x)[i];
    float4 w = *(const float4*)(w3 + d4 * 4);
    v.x *= w.x; v.y *= w.y; v.z *= w.z; v.w *= w.w;
    ((float4*)y)[i] = v;
}

__global__ __launch_bounds__(256) void concat_kernel(
    const float* __restrict__ a, const float* __restrict__ b,
    float* __restrict__ cat)
{
    const int gid = blockIdx.x * blockDim.x + threadIdx.x;
    const int c4 = gid & 255;
    const int m  = gid >> 8;
    float4 v;
    if (c4 < 128) v = *(const float4*)(a + (long)m * U_ + c4 * 4);
    else          v = *(const float4*)(b + (long)m * U_ + (c4 - 128) * 4);
    *(float4*)(cat + (long)m * (2 * U_) + c4 * 4) = v;
}

__global__ __launch_bounds__(256) void final_kernel(
    const float* __restrict__ r, const float* __restrict__ z,
    const float* __restrict__ inp, float* __restrict__ out, int n4)
{
    const int i = blockIdx.x * blockDim.x + threadIdx.x;
    if (i >= n4) return;
    const float4 rv = ((const float4*)r)[i];
    const float4 zv = ((const float4*)z)[i];
    const float4 iv = ((const float4*)inp)[i];
    float4 o;
    o.x = rv.x * iv.x + zv.x * zv.x;
    o.y = rv.y * iv.y + zv.y * zv.y;
    o.z = rv.z * iv.z + zv.z * zv.z;
    o.w = rv.w * iv.w + zv.w * zv.w;
    ((float4*)out)[i] = o;
}

// ---------------------------------------------------------------------------
// Launch
// ---------------------------------------------------------------------------
#define GEMM_SMEM (4 * STAGE_F * 4)   // 4 stage-buffers (A0,A1,B0,B1) of floats

extern "C" void kernel_launch(void* const* d_in, const int* in_sizes, int n_in,
                              void* d_out, int out_size)
{
    (void)in_sizes; (void)n_in; (void)out_size;
    const float* inputs = (const float*)d_in[0];
    const float* tW     = (const float*)d_in[1];
    const float* tb     = (const float*)d_in[2];
    const float* cW     = (const float*)d_in[3];
    const float* cb     = (const float*)d_in[4];
    const float* aW     = (const float*)d_in[5];
    const float* ab     = (const float*)d_in[6];
    const float* frW    = (const float*)d_in[7];
    const float* frb    = (const float*)d_in[8];
    const float* ffW    = (const float*)d_in[9];
    const float* ffb    = (const float*)d_in[10];
    float* out = (float*)d_out;

    float *x0, *x1, *t, *c, *Amat, *s1, *s2, *cat, *tWt, *cWt, *ffWt, *frWt, *x1t;
    cudaGetSymbolAddress((void**)&x0,   g_x0);
    cudaGetSymbolAddress((void**)&x1,   g_x1);
    cudaGetSymbolAddress((void**)&t,    g_t);
    cudaGetSymbolAddress((void**)&c,    g_c);
    cudaGetSymbolAddress((void**)&Amat, g_A);
    cudaGetSymbolAddress((void**)&s1,   g_s1);
    cudaGetSymbolAddress((void**)&s2,   g_s2);
    cudaGetSymbolAddress((void**)&cat,  g_cat);
    cudaGetSymbolAddress((void**)&tWt,  g_tWt);
    cudaGetSymbolAddress((void**)&cWt,  g_cWt);
    cudaGetSymbolAddress((void**)&ffWt, g_ffWt);
    cudaGetSymbolAddress((void**)&frWt, g_frWt);
    cudaGetSymbolAddress((void**)&x1t,  g_x1t);

    cudaFuncSetAttribute(gemm_mma, cudaFuncAttributeMaxDynamicSharedMemorySize,
                         GEMM_SMEM);

    const int n4  = M_ * U_ / 4;
    const int ewg = (n4 + 255) / 256;

    // weight transposes
    transpose_k<<<dim3(16,16,2), 256>>>(tW, tWt, U_, U_, (long)U_*U_, (long)U_*U_);
    transpose_k<<<dim3(16,16,2), 256>>>(cW, cWt, U_, U_, (long)U_*U_, (long)U_*U_);
    transpose_k<<<dim3(16,32,1), 256>>>(ffW, ffWt, 2*U_, U_, 0, 0);
    transpose_k<<<dim3(16,32,1), 256>>>(frW, frWt, 2*U_, U_, 0, 0);

    dim3 gHW(U_/128, M_/128, 1);   // (4,128)
    // highway layer 0
    gemm_mma<<<gHW, 256, GEMM_SMEM>>>(inputs, U_, 0, tWt, U_, 0, t, U_, 0, U_,
                                      nullptr, 0, tb, 0, nullptr, 1);
    gemm_mma<<<gHW, 256, GEMM_SMEM>>>(inputs, U_, 0, cWt, U_, 0, c, U_, 0, U_,
                                      nullptr, 0, cb, 0, nullptr, 2);
    highway_combine<<<ewg, 256>>>(t, c, inputs, x0, n4);
    // highway layer 1
    gemm_mma<<<gHW, 256, GEMM_SMEM>>>(x0, U_, 0, tWt + U_*U_, U_, 0, t, U_, 0, U_,
                                      nullptr, 0, tb + U_, 0, nullptr, 1);
    gemm_mma<<<gHW, 256, GEMM_SMEM>>>(x0, U_, 0, cWt + U_*U_, U_, 0, c, U_, 0, U_,
                                      nullptr, 0, cb + U_, 0, nullptr, 2);
    highway_combine<<<ewg, 256>>>(t, c, x0, x1, n4);

    // s1, s2, xw3, x1^T
    s1s2_kernel<<<M_/8, 256>>>(x1, aW, s1, s2);
    mulw3_kernel<<<ewg, 256>>>(x1, aW + 2*U_, t, n4);          // t = x1 * w3
    transpose_k<<<dim3(16,32,B_), 256>>>(x1, x1t, L_, U_, (long)L_*U_, (long)U_*L_);

    // scores: A[b] = relu( (x1*w3) @ x1^T + s1 + s2 + ab )
    dim3 gS(L_/128, L_/128, B_);   // (8,8,16)
    gemm_mma<<<gS, 256, GEMM_SMEM>>>(t, U_, (long)L_*U_, x1, U_, (long)L_*U_,
                                     Amat, L_, (long)L_*L_, U_,
                                     s1, L_, s2, L_, ab, 1);

    softmax_kernel<<<M_, 256>>>(Amat);

    // att = P @ x1 -> c
    dim3 gAtt(U_/128, L_/128, B_); // (4,8,16)
    gemm_mma<<<gAtt, 256, GEMM_SMEM>>>(Amat, L_, (long)L_*L_, x1t, L_, (long)U_*L_,
                                       c, U_, (long)L_*U_, L_,
                                       nullptr, 0, nullptr, 0, nullptr, 0);

    // concat [inputs, att]
    const int cg = (M_ * 2 * U_ / 4 + 255) / 256;
    concat_kernel<<<cg, 256>>>(inputs, c, cat);

    // z -> x0, r -> t
    gemm_mma<<<gHW, 256, GEMM_SMEM>>>(cat, 2*U_, 0, ffWt, 2*U_, 0, x0, U_, 0, 2*U_,
                                      nullptr, 0, ffb, 0, nullptr, 2);
    gemm_mma<<<gHW, 256, GEMM_SMEM>>>(cat, 2*U_, 0, frWt, 2*U_, 0, t, U_, 0, 2*U_,
                                      nullptr, 0, frb, 0, nullptr, 2);

    // out = r*inputs + z*z
    final_kernel<<<ewg, 256>>>(t, x0, inputs, out, n4);
}

// round 4
// speedup vs baseline: 5.1029x; 1.9732x over previous
#include <cuda_runtime.h>
#include <cuda_bf16.h>
#include <cstdint>

#define B_  16
#define L_  1024
#define U_  512
#define M_  (B_*L_)      // 16384

typedef __nv_bfloat16  bf16;
typedef __nv_bfloat162 bf162;

// ---------------------------------------------------------------------------
// Scratch (device globals; no allocation allowed)
// ---------------------------------------------------------------------------
__device__ float g_x0[M_*U_];
__device__ float g_x1[M_*U_];
__device__ float g_t [M_*U_];
__device__ float g_c [M_*U_];
__device__ float g_A [(size_t)B_*L_*L_];
__device__ float g_s1[M_];
__device__ float g_s2[M_];

__device__ bf16 g_ib  [M_*U_];          // inputs bf16
__device__ bf16 g_x0b [M_*U_];
__device__ bf16 g_x1b [M_*U_];
__device__ bf16 g_xw3 [M_*U_];          // x1 * w3 (bf16)
__device__ bf16 g_x1t [M_*U_];          // per-batch [U][L]
__device__ bf16 g_cat [(size_t)M_*2*U_];
__device__ bf16 g_Ab  [(size_t)B_*L_*L_];
__device__ bf16 g_tWt [2*U_*U_];
__device__ bf16 g_cWt [2*U_*U_];
__device__ bf16 g_ffWt[2*U_*U_];        // [512][1024]
__device__ bf16 g_frWt[2*U_*U_];        // [512][1024]

// ---------------------------------------------------------------------------
// PTX helpers (baseline PTX; compile at compute_103)
// ---------------------------------------------------------------------------
__device__ __forceinline__ uint32_t smem_u32(const void* p) {
    uint32_t a;
    asm("{ .reg .u64 t; cvta.to.shared.u64 t, %1; cvt.u32.u64 %0, t; }"
        : "=r"(a) : "l"(p));
    return a;
}
__device__ __forceinline__ void cpasync16(uint32_t dst, const void* src) {
    asm volatile("cp.async.cg.shared.global [%0], [%1], 16;"
                 :: "r"(dst), "l"(src));
}
#define CP_COMMIT() asm volatile("cp.async.commit_group;" ::: "memory")
#define CP_WAIT(n)  asm volatile("cp.async.wait_group %0;" :: "n"(n) : "memory")

#define LDSM4(r0, r1, r2, r3, addr) \
    asm volatile("ldmatrix.sync.aligned.m8n8.x4.shared.b16 {%0,%1,%2,%3}, [%4];" \
        : "=r"(r0), "=r"(r1), "=r"(r2), "=r"(r3) : "r"(addr))

__device__ __forceinline__ void mma_bf16(float* c, const uint32_t* a,
                                         uint32_t b0, uint32_t b1) {
    asm volatile(
        "mma.sync.aligned.m16n8k16.row.col.f32.bf16.bf16.f32 "
        "{%0,%1,%2,%3}, {%4,%5,%6,%7}, {%8,%9}, {%0,%1,%2,%3};"
        : "+f"(c[0]), "+f"(c[1]), "+f"(c[2]), "+f"(c[3])
        : "r"(a[0]), "r"(a[1]), "r"(a[2]), "r"(a[3]), "r"(b0), "r"(b1));
}

// ---------------------------------------------------------------------------
// bf16 tensor-core GEMM:
//   C[M,N] = act( sum_k A[m,k]*Bt[n,k] + rowbias[m] + colbias[n] + addc )
// A row-major bf16 [*, lda]; Bt row-major bf16 [N, K].
// Outputs: fp32 C (nullable) and/or bf16 Cb (nullable).
// Grid (N/128, M/128, batch), 256 threads, warp tile 64x32.
// Double-buffered cp.async, KC=64, SW128 smem swizzle, ldmatrix frags.
// ---------------------------------------------------------------------------
#define KC 64
#define RB 128                 // row bytes (KC bf16)
#define STAGE_B (128*RB)       // 16 KB

__global__ __launch_bounds__(256) void gemm_bf(
    const bf16* __restrict__ A,  long lda, long sA,
    const bf16* __restrict__ Bt, long ldb, long sB,
    float* __restrict__ C, long ldc, long sC,
    bf16* __restrict__ Cb, long ldcb, long sCb,
    int K,
    const float* __restrict__ rowbias, long srb,
    const float* __restrict__ colbias, long scb,
    const float* __restrict__ addc,
    int act)
{
    extern __shared__ char smc[];
    const uint32_t as0 = smem_u32(smc);            // A: 2 stages
    const uint32_t bs0 = as0 + 2 * STAGE_B;        // B: 2 stages

    const int tid  = threadIdx.x;
    const int wid  = tid >> 5;
    const int lane = tid & 31;
    const int li   = lane & 7;
    const int q    = lane >> 3;
    const int ql   = q & 1;
    const int qh   = q >> 1;
    const int m0   = (wid >> 2) * 64;
    const int n0   = (wid & 3)  * 32;

    const int bz = blockIdx.z;
    const int bm = blockIdx.y * 128;
    const int bn = blockIdx.x * 128;

    const bf16* Ab = A  + (long)bz * sA;
    const bf16* Bb = Bt + (long)bz * sB;

    const int lrow = tid >> 1;              // 0..127
    const int lcb  = (tid & 1) * 4;         // chunk base (of 8 per row)
    const int nch  = K / KC;

    float acc[4][4][4];
    #pragma unroll
    for (int i = 0; i < 4; i++)
        #pragma unroll
        for (int j = 0; j < 4; j++)
            #pragma unroll
            for (int k = 0; k < 4; k++) acc[i][j][k] = 0.f;

    auto load_chunk = [&](int c, int st) {
        const bf16* ap = Ab + (long)(bm + lrow) * lda + c * KC;
        const bf16* bp = Bb + (long)(bn + lrow) * ldb + c * KC;
        const uint32_t ad = as0 + st * STAGE_B + lrow * RB;
        const uint32_t bd = bs0 + st * STAGE_B + lrow * RB;
        const int sw = lrow & 7;
        #pragma unroll
        for (int j = 0; j < 4; j++) {
            const int ch = lcb + j;
            cpasync16(ad + ((ch ^ sw) * 16), ap + ch * 8);
            cpasync16(bd + ((ch ^ sw) * 16), bp + ch * 8);
        }
    };

    load_chunk(0, 0);
    CP_COMMIT();

    // precomputed fragment rows
    int rA[4], nB[2];
    #pragma unroll
    for (int mt = 0; mt < 4; mt++) rA[mt] = m0 + mt * 16 + li + ql * 8;
    #pragma unroll
    for (int p = 0; p < 2; p++)    nB[p] = n0 + p * 16 + qh * 8 + li;

    for (int c = 0; c < nch; c++) {
        const int st = c & 1;
        if (c + 1 < nch) { load_chunk(c + 1, st ^ 1); CP_COMMIT(); CP_WAIT(1); }
        else             { CP_WAIT(0); }
        __syncthreads();

        const uint32_t asb = as0 + st * STAGE_B;
        const uint32_t bsb = bs0 + st * STAGE_B;

        #pragma unroll
        for (int ks = 0; ks < 4; ks++) {
            uint32_t a[4][4];
            #pragma unroll
            for (int mt = 0; mt < 4; mt++) {
                const int r = rA[mt];
                const int ch = (ks * 2 + qh) ^ (r & 7);
                LDSM4(a[mt][0], a[mt][1], a[mt][2], a[mt][3],
                      asb + r * RB + ch * 16);
            }
            uint32_t b[2][4];
            #pragma unroll
            for (int p = 0; p < 2; p++) {
                const int n = nB[p];
                const int ch = (ks * 2 + ql) ^ (n & 7);
                LDSM4(b[p][0], b[p][1], b[p][2], b[p][3],
                      bsb + n * RB + ch * 16);
            }
            #pragma unroll
            for (int nt = 0; nt < 4; nt++) {
                const uint32_t b0 = b[nt >> 1][(nt & 1) * 2];
                const uint32_t b1 = b[nt >> 1][(nt & 1) * 2 + 1];
                #pragma unroll
                for (int mt = 0; mt < 4; mt++)
                    mma_bf16(acc[mt][nt], a[mt], b0, b1);
            }
        }
        __syncthreads();
    }

    // ---- epilogue ----
    const int grp = lane >> 2;     // 0..7
    const int tig = lane & 3;      // 0..3
    float* Cp  = C  ? C  + (long)bz * sC  : nullptr;
    bf16*  Cbp = Cb ? Cb + (long)bz * sCb : nullptr;
    const float a0 = addc ? addc[0] : 0.f;

    #pragma unroll
    for (int mt = 0; mt < 4; mt++) {
        const int row = bm + m0 + mt * 16 + grp;
        float rb0 = a0, rb8 = a0;
        if (rowbias) {
            rb0 += rowbias[(long)bz * srb + row];
            rb8 += rowbias[(long)bz * srb + row + 8];
        }
        #pragma unroll
        for (int nt = 0; nt < 4; nt++) {
            const int col = bn + n0 + nt * 8 + tig * 2;
            float cb0 = 0.f, cb1 = 0.f;
            if (colbias) {
                cb0 = colbias[(long)bz * scb + col];
                cb1 = colbias[(long)bz * scb + col + 1];
            }
            float v0 = acc[mt][nt][0] + rb0 + cb0;
            float v1 = acc[mt][nt][1] + rb0 + cb1;
            float v2 = acc[mt][nt][2] + rb8 + cb0;
            float v3 = acc[mt][nt][3] + rb8 + cb1;
            if (act == 1) {
                v0 = fmaxf(v0, 0.f); v1 = fmaxf(v1, 0.f);
                v2 = fmaxf(v2, 0.f); v3 = fmaxf(v3, 0.f);
            } else if (act == 2) {
                v0 = 1.f / (1.f + __expf(-v0)); v1 = 1.f / (1.f + __expf(-v1));
                v2 = 1.f / (1.f + __expf(-v2)); v3 = 1.f / (1.f + __expf(-v3));
            }
            if (Cp) {
                *(float2*)(Cp + (long)row * ldc + col)       = make_float2(v0, v1);
                *(float2*)(Cp + (long)(row + 8) * ldc + col) = make_float2(v2, v3);
            }
            if (Cbp) {
                *(bf162*)(Cbp + (long)row * ldcb + col)       = __floats2bfloat162_rn(v0, v1);
                *(bf162*)(Cbp + (long)(row + 8) * ldcb + col) = __floats2bfloat162_rn(v2, v3);
            }
        }
    }
}

// ---------------------------------------------------------------------------
// fp32 -> bf16 transpose: dst[c][r] = src[r][c]; grid (C/32, R/32, batch)
// ---------------------------------------------------------------------------
__global__ __launch_bounds__(256) void transpose_b(
    const float* __restrict__ src, bf16* __restrict__ dst,
    int R, int Cc, long ssrc, long sdst)
{
    __shared__ float tile[32][33];
    src += (long)blockIdx.z * ssrc;
    dst += (long)blockIdx.z * sdst;
    const int r0 = blockIdx.y * 32, c0 = blockIdx.x * 32;
    const int tx = threadIdx.x & 31, ty = threadIdx.x >> 5;
    #pragma unroll
    for (int i = 0; i < 32; i += 8)
        tile[ty + i][tx] = src[(long)(r0 + ty + i) * Cc + c0 + tx];
    __syncthreads();
    #pragma unroll
    for (int i = 0; i < 32; i += 8)
        dst[(long)(c0 + ty + i) * R + r0 + tx] = __float2bfloat16(tile[tx][ty + i]);
}

// ---------------------------------------------------------------------------
// Small kernels
// ---------------------------------------------------------------------------
// inputs fp32 -> g_ib bf16, and into cat[:, 0:512]
__global__ __launch_bounds__(256) void conv_inputs(
    const float* __restrict__ in, bf16* __restrict__ ib, bf16* __restrict__ cat)
{
    const int i = blockIdx.x * 256 + threadIdx.x;    // over M*U/4
    const float4 v = ((const float4*)in)[i];
    const bf162 p0 = __floats2bfloat162_rn(v.x, v.y);
    const bf162 p1 = __floats2bfloat162_rn(v.z, v.w);
    *(bf162*)(ib + (long)i * 4)     = p0;
    *(bf162*)(ib + (long)i * 4 + 2) = p1;
    const int m  = i >> 7;          // U/4 = 128
    const int c4 = i & 127;
    bf16* cr = cat + (long)m * (2 * U_) + c4 * 4;
    *(bf162*)cr       = p0;
    *(bf162*)(cr + 2) = p1;
}

// highway combine: xo = t*c + x*(1-c); writes fp32 + bf16
__global__ __launch_bounds__(256) void highway_combine(
    const float* __restrict__ t, const float* __restrict__ c,
    const float* __restrict__ xin, float* __restrict__ xo,
    bf16* __restrict__ xob, int n4)
{
    const int i = blockIdx.x * blockDim.x + threadIdx.x;
    if (i >= n4) return;
    const float4 tv = ((const float4*)t)[i];
    const float4 cv = ((const float4*)c)[i];
    const float4 xv = ((const float4*)xin)[i];
    float4 o;
    o.x = tv.x * cv.x + xv.x * (1.f - cv.x);
    o.y = tv.y * cv.y + xv.y * (1.f - cv.y);
    o.z = tv.z * cv.z + xv.z * (1.f - cv.z);
    o.w = tv.w * cv.w + xv.w * (1.f - cv.w);
    ((float4*)xo)[i] = o;
    *(bf162*)(xob + (long)i * 4)     = __floats2bfloat162_rn(o.x, o.y);
    *(bf162*)(xob + (long)i * 4 + 2) = __floats2bfloat162_rn(o.z, o.w);
}

// xw3 = x * w3  (bf16 out)
__global__ __launch_bounds__(256) void mulw3_kernel(
    const float* __restrict__ x, const float* __restrict__ w3,
    bf16* __restrict__ y, int n4)
{
    const int i = blockIdx.x * blockDim.x + threadIdx.x;
    if (i >= n4) return;
    const int d4 = i & (U_ / 4 - 1);
    float4 v = ((const float4*)x)[i];
    const float4 w = *(const float4*)(w3 + d4 * 4);
    v.x *= w.x; v.y *= w.y; v.z *= w.z; v.w *= w.w;
    *(bf162*)(y + (long)i * 4)     = __floats2bfloat162_rn(v.x, v.y);
    *(bf162*)(y + (long)i * 4 + 2) = __floats2bfloat162_rn(v.z, v.w);
}

// s1[b,i], s2[b,i]
__global__ __launch_bounds__(256) void s1s2_kernel(
    const float* __restrict__ x, const float* __restrict__ aW,
    float* __restrict__ s1, float* __restrict__ s2)
{
    const int row  = blockIdx.x * 8 + (threadIdx.x >> 5);
    const int lane = threadIdx.x & 31;
    const float* xr = x + (long)row * U_;
    float a = 0.f, b = 0.f;
    for (int d = lane; d < U_; d += 32) {
        const float xv = xr[d];
        a += xv * aW[d];
        b += xv * aW[U_ + d];
    }
    #pragma unroll
    for (int o = 16; o > 0; o >>= 1) {
        a += __shfl_xor_sync(0xffffffffu, a, o);
        b += __shfl_xor_sync(0xffffffffu, b, o);
    }
    if (lane == 0) { s1[row] = a; s2[row] = b; }
}

// softmax: fp32 in, bf16 out (register-resident single pass)
__global__ __launch_bounds__(256) void softmax_b(
    const float* __restrict__ A, bf16* __restrict__ Ab)
{
    const float* row = A  + (long)blockIdx.x * L_;
    bf16*        orow = Ab + (long)blockIdx.x * L_;
    const int tid = threadIdx.x;
    __shared__ float red[256];

    float4 v = ((const float4*)row)[tid];
    float m = fmaxf(fmaxf(v.x, v.y), fmaxf(v.z, v.w));
    red[tid] = m; __syncthreads();
    for (int s = 128; s > 0; s >>= 1) {
        if (tid < s) red[tid] = fmaxf(red[tid], red[tid + s]);
        __syncthreads();
    }
    m = red[0]; __syncthreads();

    v.x = __expf(v.x - m); v.y = __expf(v.y - m);
    v.z = __expf(v.z - m); v.w = __expf(v.w - m);
    red[tid] = v.x + v.y + v.z + v.w; __syncthreads();
    for (int s = 128; s > 0; s >>= 1) {
        if (tid < s) red[tid] += red[tid + s];
        __syncthreads();
    }
    const float inv = 1.f / red[0];
    *(bf162*)(orow + (long)tid * 4)     = __floats2bfloat162_rn(v.x * inv, v.y * inv);
    *(bf162*)(orow + (long)tid * 4 + 2) = __floats2bfloat162_rn(v.z * inv, v.w * inv);
}

// out = r*inputs + z*z
__global__ __launch_bounds__(256) void final_kernel(
    const float* __restrict__ r, const float* __restrict__ z,
    const float* __restrict__ inp, float* __restrict__ out, int n4)
{
    const int i = blockIdx.x * blockDim.x + threadIdx.x;
    if (i >= n4) return;
    const float4 rv = ((const float4*)r)[i];
    const float4 zv = ((const float4*)z)[i];
    const float4 iv = ((const float4*)inp)[i];
    float4 o;
    o.x = rv.x * iv.x + zv.x * zv.x;
    o.y = rv.y * iv.y + zv.y * zv.y;
    o.z = rv.z * iv.z + zv.z * zv.z;
    o.w = rv.w * iv.w + zv.w * zv.w;
    ((float4*)out)[i] = o;
}

// ---------------------------------------------------------------------------
// Launch
// ---------------------------------------------------------------------------
#define GEMM_SMEM (4 * STAGE_B)   // 64 KB

extern "C" void kernel_launch(void* const* d_in, const int* in_sizes, int n_in,
                              void* d_out, int out_size)
{
    (void)in_sizes; (void)n_in; (void)out_size;
    const float* inputs = (const float*)d_in[0];
    const float* tW     = (const float*)d_in[1];
    const float* tb     = (const float*)d_in[2];
    const float* cW     = (const float*)d_in[3];
    const float* cb     = (const float*)d_in[4];
    const float* aW     = (const float*)d_in[5];
    const float* ab     = (const float*)d_in[6];
    const float* frW    = (const float*)d_in[7];
    const float* frb    = (const float*)d_in[8];
    const float* ffW    = (const float*)d_in[9];
    const float* ffb    = (const float*)d_in[10];
    float* out = (float*)d_out;

    float *x0, *x1, *t, *c, *Amat, *s1, *s2;
    bf16 *ib, *x0b, *x1b, *xw3, *x1t, *cat, *Ab, *tWt, *cWt, *ffWt, *frWt;
    cudaGetSymbolAddress((void**)&x0,   g_x0);
    cudaGetSymbolAddress((void**)&x1,   g_x1);
    cudaGetSymbolAddress((void**)&t,    g_t);
    cudaGetSymbolAddress((void**)&c,    g_c);
    cudaGetSymbolAddress((void**)&Amat, g_A);
    cudaGetSymbolAddress((void**)&s1,   g_s1);
    cudaGetSymbolAddress((void**)&s2,   g_s2);
    cudaGetSymbolAddress((void**)&ib,   g_ib);
    cudaGetSymbolAddress((void**)&x0b,  g_x0b);
    cudaGetSymbolAddress((void**)&x1b,  g_x1b);
    cudaGetSymbolAddress((void**)&xw3,  g_xw3);
    cudaGetSymbolAddress((void**)&x1t,  g_x1t);
    cudaGetSymbolAddress((void**)&cat,  g_cat);
    cudaGetSymbolAddress((void**)&Ab,   g_Ab);
    cudaGetSymbolAddress((void**)&tWt,  g_tWt);
    cudaGetSymbolAddress((void**)&cWt,  g_cWt);
    cudaGetSymbolAddress((void**)&ffWt, g_ffWt);
    cudaGetSymbolAddress((void**)&frWt, g_frWt);

    cudaFuncSetAttribute(gemm_bf, cudaFuncAttributeMaxDynamicSharedMemorySize,
                         GEMM_SMEM);

    const int n4  = M_ * U_ / 4;
    const int ewg = (n4 + 255) / 256;

    // weight conversions (fp32 -> bf16, transposed)
    transpose_b<<<dim3(16,16,2), 256>>>(tW, tWt, U_, U_, (long)U_*U_, (long)U_*U_);
    transpose_b<<<dim3(16,16,2), 256>>>(cW, cWt, U_, U_, (long)U_*U_, (long)U_*U_);
    transpose_b<<<dim3(16,32,1), 256>>>(ffW, ffWt, 2*U_, U_, 0, 0);
    transpose_b<<<dim3(16,32,1), 256>>>(frW, frWt, 2*U_, U_, 0, 0);
    // inputs -> bf16 + cat first half
    conv_inputs<<<ewg, 256>>>(inputs, ib, cat);

    dim3 gHW(U_/128, M_/128, 1);   // (4,128)
    // highway layer 0
    gemm_bf<<<gHW, 256, GEMM_SMEM>>>(ib, U_, 0, tWt, U_, 0, t, U_, 0,
                                     nullptr, 0, 0, U_, nullptr, 0, tb, 0, nullptr, 1);
    gemm_bf<<<gHW, 256, GEMM_SMEM>>>(ib, U_, 0, cWt, U_, 0, c, U_, 0,
                                     nullptr, 0, 0, U_, nullptr, 0, cb, 0, nullptr, 2);
    highway_combine<<<ewg, 256>>>(t, c, inputs, x0, x0b, n4);
    // highway layer 1
    gemm_bf<<<gHW, 256, GEMM_SMEM>>>(x0b, U_, 0, tWt + U_*U_, U_, 0, t, U_, 0,
                                     nullptr, 0, 0, U_, nullptr, 0, tb + U_, 0, nullptr, 1);
    gemm_bf<<<gHW, 256, GEMM_SMEM>>>(x0b, U_, 0, cWt + U_*U_, U_, 0, c, U_, 0,
                                     nullptr, 0, 0, U_, nullptr, 0, cb + U_, 0, nullptr, 2);
    highway_combine<<<ewg, 256>>>(t, c, x0, x1, x1b, n4);

    // s1, s2, xw3, x1^T
    s1s2_kernel<<<M_/8, 256>>>(x1, aW, s1, s2);
    mulw3_kernel<<<ewg, 256>>>(x1, aW + 2*U_, xw3, n4);
    transpose_b<<<dim3(16,32,B_), 256>>>(x1, x1t, L_, U_, (long)L_*U_, (long)U_*L_);

    // scores: A[b] = relu( (x1*w3) @ x1^T + s1 + s2 + ab )  -> fp32 Amat
    dim3 gS(L_/128, L_/128, B_);
    gemm_bf<<<gS, 256, GEMM_SMEM>>>(xw3, U_, (long)L_*U_, x1b, U_, (long)L_*U_,
                                    Amat, L_, (long)L_*L_,
                                    nullptr, 0, 0, U_,
                                    s1, L_, s2, L_, ab, 1);

    // softmax -> bf16 Ab
    softmax_b<<<M_, 256>>>(Amat, Ab);

    // att = P @ x1 -> bf16 directly into cat second half
    dim3 gAtt(U_/128, L_/128, B_);
    gemm_bf<<<gAtt, 256, GEMM_SMEM>>>(Ab, L_, (long)L_*L_, x1t, L_, (long)U_*L_,
                                      nullptr, 0, 0,
                                      cat + U_, 2*U_, (long)L_*2*U_,
                                      L_, nullptr, 0, nullptr, 0, nullptr, 0);

    // z -> t, r -> c
    gemm_bf<<<gHW, 256, GEMM_SMEM>>>(cat, 2*U_, 0, ffWt, 2*U_, 0, t, U_, 0,
                                     nullptr, 0, 0, 2*U_, nullptr, 0, ffb, 0, nullptr, 2);
    gemm_bf<<<gHW, 256, GEMM_SMEM>>>(cat, 2*U_, 0, frWt, 2*U_, 0, c, U_, 0,
                                     nullptr, 0, 0, 2*U_, nullptr, 0, frb, 0, nullptr, 2);

    // out = r*inputs + z*z
    final_kernel<<<ewg, 256>>>(c, t, inputs, out, n4);
}